// round 8
// baseline (speedup 1.0000x reference)
#include <cuda_runtime.h>
#include <cstdint>

#define B_      32
#define N_      500
#define D_      2048
#define K_      128
#define SIGMA   0.05f
#define THREADS 512          // 4 contiguous elements per thread
#define PREPT   256

__device__ float g_xk[B_];   // safe lower bound of K-th largest of x per row

// monotone float -> uint (bigger float -> bigger uint)
__device__ __forceinline__ unsigned int f2u(float f) {
    unsigned int u = __float_as_uint(f);
    return u ^ (((unsigned int)((int)u >> 31)) | 0x80000000u);
}
__device__ __forceinline__ float u2f(unsigned int u) {
    unsigned int v = (u & 0x80000000u) ? (u ^ 0x80000000u) : ~u;
    return __uint_as_float(v);
}

// exclusive block scan over 512 threads (16 warps); returns total.
// Dedicated warpSums buffer per call site; no trailing barrier.
__device__ __forceinline__ unsigned int block_scan_excl(unsigned int v,
                                                        unsigned int* warpSums,
                                                        unsigned int* total) {
    const int lane = threadIdx.x & 31;
    const int wid  = threadIdx.x >> 5;
    unsigned int x = v;
    #pragma unroll
    for (int o = 1; o < 32; o <<= 1) {
        unsigned int y = __shfl_up_sync(0xffffffffu, x, o);
        if (lane >= o) x += y;
    }
    if (lane == 31) warpSums[wid] = x;
    __syncthreads();
    if (wid == 0 && lane < 16) {
        unsigned int s = warpSums[lane];
        #pragma unroll
        for (int o = 1; o < 16; o <<= 1) {
            unsigned int y = __shfl_up_sync(0xffffu, s, o);
            if (lane >= o) s += y;
        }
        warpSums[lane] = s;
    }
    __syncthreads();
    unsigned int base = (wid > 0) ? warpSums[wid - 1] : 0u;
    *total = warpSums[15];
    return base + x - v;
}

// ---- prep kernel: blocks 0..31 compute xK(row); blocks 32.. zero `ind` ----
#define PREP_BLOCKS 2048
__global__ __launch_bounds__(PREPT)
void prep_kernel(const float* __restrict__ x, float4* __restrict__ ind4, int n4) {
    __shared__ unsigned int hist[256];
    __shared__ unsigned int sh_sel, sh_krem, sh_done;

    const int t = threadIdx.x;

    if (blockIdx.x >= B_) {
        if (ind4) {
            float4 z = make_float4(0.f, 0.f, 0.f, 0.f);
            int stride = (PREP_BLOCKS - B_) * PREPT;
            for (int i = (blockIdx.x - B_) * PREPT + t; i < n4; i += stride)
                ind4[i] = z;
        }
        return;
    }

    const int lane = t & 31, wid = t >> 5;
    const int b = blockIdx.x;

    unsigned int k[8];
    {
        const float4* xv = (const float4*)(x + (size_t)b * D_);
        float4 a = xv[2 * t], c = xv[2 * t + 1];
        k[0] = f2u(a.x); k[1] = f2u(a.y); k[2] = f2u(a.z); k[3] = f2u(a.w);
        k[4] = f2u(c.x); k[5] = f2u(c.y); k[6] = f2u(c.z); k[7] = f2u(c.w);
    }

    unsigned int pref = 0, maskH = 0, krem = K_, done = 0;
    for (int pass = 0; pass < 4; pass++) {
        const int shift = 24 - pass * 8;
        hist[t] = 0u;
        __syncthreads();
        #pragma unroll
        for (int i = 0; i < 8; i++) {
            unsigned int kk = k[i];
            if ((kk & maskH) == pref)
                atomicAdd(&hist[(kk >> shift) & 0xFFu], 1u);
        }
        __syncthreads();
        if (wid == 0) {
            unsigned int c[8], s = 0;
            #pragma unroll
            for (int i = 0; i < 8; i++) { c[i] = hist[lane * 8 + i]; s += c[i]; }
            unsigned int xs = s;
            #pragma unroll
            for (int o = 1; o < 32; o <<= 1) {
                unsigned int y = __shfl_up_sync(0xffffffffu, xs, o);
                if (lane >= o) xs += y;
            }
            unsigned int tot = __shfl_sync(0xffffffffu, xs, 31);
            unsigned int run = xs - s;
            #pragma unroll
            for (int i = 0; i < 8; i++) {
                unsigned int sfx = tot - run, after = sfx - c[i];
                if (sfx >= krem && after < krem) {
                    sh_sel = (unsigned int)(lane * 8 + i);
                    sh_krem = krem - after;
                    sh_done = (sfx == krem);
                }
                run += c[i];
            }
        }
        __syncthreads();
        pref |= (sh_sel << shift); maskH |= (0xFFu << shift);
        krem = sh_krem; done = sh_done;
        if (done) break;
    }
    if (t == 0) g_xk[b] = u2f(pref);
}

// ---- main kernel: one CTA per (b, n) sample ----
__global__ __launch_bounds__(THREADS)
void perturbed_topk_kernel(const float* __restrict__ x,
                           const float* __restrict__ noise,
                           float* __restrict__ ind,    // (B,K,D) or null
                           float* __restrict__ idxf)   // (B,N,K) or null
{
    __shared__ unsigned int   ckey[D_];
    __shared__ unsigned short cidx[D_];
    __shared__ unsigned int   hist[256];
    __shared__ unsigned int   scanA[16], scanB[16];
    __shared__ float          warpMax[16];
    __shared__ float          sh_L;
    __shared__ unsigned int   sh_sel, sh_krem, sh_done;

    const int t = threadIdx.x, lane = t & 31, wid = t >> 5;
    const int b = blockIdx.x / N_;

    // load + perturb; keys converted to uint immediately (kf does not persist)
    unsigned int ku[4];
    float am;
    {
        float4 X = ((const float4*)(x + (size_t)b * D_))[t];
        float4 Nz = ((const float4*)(noise + (size_t)blockIdx.x * D_))[t];
        ku[0] = f2u(fmaf(SIGMA, Nz.x, X.x));
        ku[1] = f2u(fmaf(SIGMA, Nz.y, X.y));
        ku[2] = f2u(fmaf(SIGMA, Nz.z, X.z));
        ku[3] = f2u(fmaf(SIGMA, Nz.w, X.w));
        am = fmaxf(fmaxf(fabsf(Nz.x), fabsf(Nz.y)),
                   fmaxf(fabsf(Nz.z), fabsf(Nz.w)));
    }
    #pragma unroll
    for (int o = 16; o > 0; o >>= 1)
        am = fmaxf(am, __shfl_xor_sync(0xffffffffu, am, o));
    if (lane == 0) warpMax[wid] = am;
    __syncthreads();
    if (t == 0) {
        float m = warpMax[0];
        #pragma unroll
        for (int w = 1; w < 16; w++) m = fmaxf(m, warpMax[w]);
        sh_L = g_xk[b] - SIGMA * m - 1e-4f;   // safe lower bound on K-th key
    }
    __syncthreads();
    const unsigned int Lu = f2u(sh_L);

    // candidate mask + compaction (ascending index order preserved)
    unsigned int m4 = 0;
    #pragma unroll
    for (int i = 0; i < 4; i++)
        m4 |= (ku[i] >= Lu) ? (1u << i) : 0u;

    unsigned int tot;
    unsigned int pos = block_scan_excl(__popc(m4), scanA, &tot);
    const int cnt = (int)tot;          // >= K guaranteed, <= 2048

    unsigned int mm = m4;
    while (mm) {
        int i = __ffs(mm) - 1;
        mm &= mm - 1;
        ckey[pos] = ku[i];
        cidx[pos] = (unsigned short)(4 * t + i);
        pos++;
    }
    __syncthreads();

    // radix select over cnt candidates (typically ~200 -> <=1 per thread)
    unsigned int pref = 0, maskH = 0, krem = K_, done = 0;
    for (int pass = 0; pass < 4; pass++) {
        const int shift = 24 - pass * 8;
        if (t < 256) hist[t] = 0u;
        __syncthreads();
        for (int i = t; i < cnt; i += THREADS) {
            unsigned int u = ckey[i];
            if ((u & maskH) == pref)
                atomicAdd(&hist[(u >> shift) & 0xFFu], 1u);
        }
        __syncthreads();
        if (wid == 0) {
            unsigned int c[8], s = 0;
            #pragma unroll
            for (int i = 0; i < 8; i++) { c[i] = hist[lane * 8 + i]; s += c[i]; }
            unsigned int xs = s;
            #pragma unroll
            for (int o = 1; o < 32; o <<= 1) {
                unsigned int y = __shfl_up_sync(0xffffffffu, xs, o);
                if (lane >= o) xs += y;
            }
            unsigned int tt = __shfl_sync(0xffffffffu, xs, 31);
            unsigned int run = xs - s;
            #pragma unroll
            for (int i = 0; i < 8; i++) {
                unsigned int sfx = tt - run, after = sfx - c[i];
                if (sfx >= krem && after < krem) {
                    sh_sel = (unsigned int)(lane * 8 + i);
                    sh_krem = krem - after;
                    sh_done = (sfx == krem);
                }
                run += c[i];
            }
        }
        __syncthreads();
        pref |= (sh_sel << shift); maskH |= (0xFFu << shift);
        krem = sh_krem; done = sh_done;
        if (done) break;
    }
    const unsigned int T = pref;
    const unsigned int R = done ? (unsigned int)K_ : krem;

    // contiguous-chunk ownership keeps array (= index) order for the rank scan
    const int ept = (cnt + THREADS - 1) / THREADS;   // usually 1
    const int beg = t * ept;
    int end = beg + ept; if (end > cnt) end = cnt;

    unsigned int gt = 0, eq = 0;
    for (int i = beg; i < end; i++) {
        unsigned int u = ckey[i];
        gt += (u > T);
        eq += (u == T);
    }
    unsigned int tot2;
    unsigned int pr = block_scan_excl(gt | (eq << 16), scanB, &tot2);
    unsigned int gtB = pr & 0xFFFFu;
    unsigned int eqB = pr >> 16;

    unsigned int j = gtB + ((eqB < R) ? eqB : R);
    unsigned int eqRank = eqB;
    const size_t idxBase = (size_t)blockIdx.x * K_;
    float* __restrict__ indRow = ind ? (ind + (size_t)b * K_ * D_) : nullptr;
    const float inv_n = 1.0f / (float)N_;

    for (int i = beg; i < end; i++) {
        unsigned int u = ckey[i];
        bool isEq = (u == T);
        bool sel  = (u > T) || (isEq && (eqRank < R));
        eqRank += isEq ? 1u : 0u;
        if (sel) {
            int e = (int)cidx[i];
            if (idxf) idxf[idxBase + j] = (float)e;
            if (indRow) atomicAdd(indRow + (size_t)j * D_ + e, inv_n);
            j++;
        }
    }
}

extern "C" void kernel_launch(void* const* d_in, const int* in_sizes, int n_in,
                              void* d_out, int out_size) {
    const float* x     = (const float*)d_in[0];
    const float* noise = (const float*)d_in[1];
    if (n_in >= 2 && in_sizes[0] != B_ * D_) {
        x     = (const float*)d_in[1];
        noise = (const float*)d_in[0];
    }

    const long long IND = (long long)B_ * K_ * D_;   // 8388608
    const long long IDX = (long long)B_ * N_ * K_;   // 2048000

    float* ind  = nullptr;
    float* idxf = nullptr;
    if ((long long)out_size >= IND + IDX) {
        ind  = (float*)d_out;
        idxf = (float*)d_out + IND;
    } else if ((long long)out_size == IND) {
        ind = (float*)d_out;
    } else if ((long long)out_size == IDX) {
        idxf = (float*)d_out;
    } else {
        ind = (float*)d_out;
    }

    prep_kernel<<<PREP_BLOCKS, PREPT>>>(x, (float4*)ind, (int)(IND / 4));
    perturbed_topk_kernel<<<B_ * N_, THREADS>>>(x, noise, ind, idxf);
}

// round 9
// speedup vs baseline: 1.5121x; 1.5121x over previous
#include <cuda_runtime.h>
#include <cstdint>

#define B_      32
#define N_      500
#define D_      2048
#define K_      128
#define SIGMA   0.05f
#define THREADS 256          // 8 contiguous elements per thread

__device__ float g_xk[B_];   // safe lower bound of K-th largest of x per row

// monotone float -> uint (bigger float -> bigger uint)
__device__ __forceinline__ unsigned int f2u(float f) {
    unsigned int u = __float_as_uint(f);
    return u ^ (((unsigned int)((int)u >> 31)) | 0x80000000u);
}
__device__ __forceinline__ float u2f(unsigned int u) {
    unsigned int v = (u & 0x80000000u) ? (u ^ 0x80000000u) : ~u;
    return __uint_as_float(v);
}

// exclusive block scan over 256 threads (8 warps); returns total.
// Dedicated warpSums buffer per call site; no trailing barrier.
__device__ __forceinline__ unsigned int block_scan_excl(unsigned int v,
                                                        unsigned int* warpSums,
                                                        unsigned int* total) {
    const int lane = threadIdx.x & 31;
    const int wid  = threadIdx.x >> 5;
    unsigned int x = v;
    #pragma unroll
    for (int o = 1; o < 32; o <<= 1) {
        unsigned int y = __shfl_up_sync(0xffffffffu, x, o);
        if (lane >= o) x += y;
    }
    if (lane == 31) warpSums[wid] = x;
    __syncthreads();
    if (wid == 0 && lane < 8) {
        unsigned int s = warpSums[lane];
        #pragma unroll
        for (int o = 1; o < 8; o <<= 1) {
            unsigned int y = __shfl_up_sync(0xffu, s, o);
            if (lane >= o) s += y;
        }
        warpSums[lane] = s;
    }
    __syncthreads();
    unsigned int base = (wid > 0) ? warpSums[wid - 1] : 0u;
    *total = warpSums[7];
    return base + x - v;
}

// ---- prep kernel: blocks 0..31 compute xK(row); blocks 32.. zero `ind` ----
#define PREP_BLOCKS 2048
__global__ __launch_bounds__(THREADS)
void prep_kernel(const float* __restrict__ x, float4* __restrict__ ind4, int n4) {
    __shared__ unsigned int hist[256];
    __shared__ unsigned int sh_sel, sh_krem, sh_done;

    const int t = threadIdx.x;

    if (blockIdx.x >= B_) {
        if (ind4) {
            float4 z = make_float4(0.f, 0.f, 0.f, 0.f);
            int stride = (PREP_BLOCKS - B_) * THREADS;
            for (int i = (blockIdx.x - B_) * THREADS + t; i < n4; i += stride)
                ind4[i] = z;
        }
        return;
    }

    const int lane = t & 31, wid = t >> 5;
    const int b = blockIdx.x;

    unsigned int k[8];
    {
        const float4* xv = (const float4*)(x + (size_t)b * D_);
        float4 a = xv[2 * t], c = xv[2 * t + 1];
        k[0] = f2u(a.x); k[1] = f2u(a.y); k[2] = f2u(a.z); k[3] = f2u(a.w);
        k[4] = f2u(c.x); k[5] = f2u(c.y); k[6] = f2u(c.z); k[7] = f2u(c.w);
    }

    unsigned int pref = 0, maskH = 0, krem = K_, done = 0;
    for (int pass = 0; pass < 4; pass++) {
        const int shift = 24 - pass * 8;
        hist[t] = 0u;
        __syncthreads();
        #pragma unroll
        for (int i = 0; i < 8; i++) {
            unsigned int kk = k[i];
            if ((kk & maskH) == pref)
                atomicAdd(&hist[(kk >> shift) & 0xFFu], 1u);
        }
        __syncthreads();
        if (wid == 0) {
            unsigned int c[8], s = 0;
            #pragma unroll
            for (int i = 0; i < 8; i++) { c[i] = hist[lane * 8 + i]; s += c[i]; }
            unsigned int xs = s;
            #pragma unroll
            for (int o = 1; o < 32; o <<= 1) {
                unsigned int y = __shfl_up_sync(0xffffffffu, xs, o);
                if (lane >= o) xs += y;
            }
            unsigned int tot = __shfl_sync(0xffffffffu, xs, 31);
            unsigned int run = xs - s;
            #pragma unroll
            for (int i = 0; i < 8; i++) {
                unsigned int sfx = tot - run, after = sfx - c[i];
                if (sfx >= krem && after < krem) {
                    sh_sel = (unsigned int)(lane * 8 + i);
                    sh_krem = krem - after;
                    sh_done = (sfx == krem);
                }
                run += c[i];
            }
        }
        __syncthreads();
        pref |= (sh_sel << shift); maskH |= (0xFFu << shift);
        krem = sh_krem; done = sh_done;
        if (done) break;
    }
    if (t == 0) g_xk[b] = u2f(pref);
}

// ---- main kernel: one CTA per (b, n) sample ----
__global__ __launch_bounds__(THREADS)
void perturbed_topk_kernel(const float* __restrict__ x,
                           const float* __restrict__ noise,
                           float* __restrict__ ind,    // (B,K,D) or null
                           float* __restrict__ idxf)   // (B,N,K) or null
{
    __shared__ unsigned int   ckey[D_];
    __shared__ unsigned short cidx[D_];
    __shared__ unsigned int   hist[256];
    __shared__ unsigned int   scanA[8], scanB[8];
    __shared__ float          warpMaxN[8], warpMaxK[8];
    __shared__ float          sh_L;
    __shared__ unsigned int   sh_Lu;
    __shared__ int            sh_p0;
    __shared__ unsigned int   sh_sel, sh_krem, sh_done;

    const int t = threadIdx.x, lane = t & 31, wid = t >> 5;
    const int b = blockIdx.x / N_;

    // load + perturb (thread t owns elems 8t..8t+7); track max|noise| and max key
    float kf[8];
    float am = 0.f, fm = -1e30f;
    {
        const float4* xv = (const float4*)(x + (size_t)b * D_);
        const float4* nv = (const float4*)(noise + (size_t)blockIdx.x * D_);
        float4 X0 = xv[2 * t], X1 = xv[2 * t + 1];
        float4 N0 = nv[2 * t], N1 = nv[2 * t + 1];
        kf[0] = fmaf(SIGMA, N0.x, X0.x); am = fmaxf(am, fabsf(N0.x)); fm = fmaxf(fm, kf[0]);
        kf[1] = fmaf(SIGMA, N0.y, X0.y); am = fmaxf(am, fabsf(N0.y)); fm = fmaxf(fm, kf[1]);
        kf[2] = fmaf(SIGMA, N0.z, X0.z); am = fmaxf(am, fabsf(N0.z)); fm = fmaxf(fm, kf[2]);
        kf[3] = fmaf(SIGMA, N0.w, X0.w); am = fmaxf(am, fabsf(N0.w)); fm = fmaxf(fm, kf[3]);
        kf[4] = fmaf(SIGMA, N1.x, X1.x); am = fmaxf(am, fabsf(N1.x)); fm = fmaxf(fm, kf[4]);
        kf[5] = fmaf(SIGMA, N1.y, X1.y); am = fmaxf(am, fabsf(N1.y)); fm = fmaxf(fm, kf[5]);
        kf[6] = fmaf(SIGMA, N1.z, X1.z); am = fmaxf(am, fabsf(N1.z)); fm = fmaxf(fm, kf[6]);
        kf[7] = fmaf(SIGMA, N1.w, X1.w); am = fmaxf(am, fabsf(N1.w)); fm = fmaxf(fm, kf[7]);
    }
    #pragma unroll
    for (int o = 16; o > 0; o >>= 1) {
        am = fmaxf(am, __shfl_xor_sync(0xffffffffu, am, o));
        fm = fmaxf(fm, __shfl_xor_sync(0xffffffffu, fm, o));
    }
    if (lane == 0) { warpMaxN[wid] = am; warpMaxK[wid] = fm; }
    __syncthreads();
    if (t == 0) {
        float m = warpMaxN[0], M = warpMaxK[0];
        #pragma unroll
        for (int w = 1; w < 8; w++) {
            m = fmaxf(m, warpMaxN[w]);
            M = fmaxf(M, warpMaxK[w]);
        }
        float L = g_xk[b] - SIGMA * m - 1e-4f;   // safe lower bound on K-th key
        unsigned int Lu = f2u(L);
        unsigned int spread = f2u(M) - Lu;       // all candidate dk in [0, spread]
        sh_L  = L;
        sh_Lu = Lu;
        // first radix pass that can contain a nonzero dk byte
        sh_p0 = (spread >> 24) ? 0 : ((spread >> 16) ? 1 : ((spread >> 8) ? 2 : 3));
    }
    __syncthreads();
    const float L = sh_L;
    const unsigned int Lu = sh_Lu;

    // candidate mask in float domain (f2u deferred to compaction)
    unsigned int m8 = 0;
    #pragma unroll
    for (int i = 0; i < 8; i++)
        m8 |= (kf[i] >= L) ? (1u << i) : 0u;

    unsigned int tot;
    unsigned int pos = block_scan_excl(__popc(m8), scanA, &tot);
    const int cnt = (int)tot;          // >= K guaranteed, <= 2048

    unsigned int mm = m8;
    while (mm) {
        int i = __ffs(mm) - 1;
        mm &= mm - 1;
        ckey[pos] = f2u(kf[i]) - Lu;   // rebased keys: order preserved, high bytes 0
        cidx[pos] = (unsigned short)(8 * t + i);
        pos++;
    }
    __syncthreads();

    // radix select over cnt rebased candidates, starting at first nonzero byte
    const int p0 = sh_p0;
    unsigned int pref = 0;
    unsigned int maskH = (p0 > 0) ? (0xFFFFFFFFu << (32 - 8 * p0)) : 0u;
    unsigned int krem = K_, done = 0;

    for (int pass = p0; pass < 4; pass++) {
        const int shift = 24 - pass * 8;
        hist[t] = 0u;
        __syncthreads();
        for (int i = t; i < cnt; i += THREADS) {
            unsigned int u = ckey[i];
            if ((u & maskH) == pref)
                atomicAdd(&hist[(u >> shift) & 0xFFu], 1u);
        }
        __syncthreads();
        if (wid == 0) {
            unsigned int c[8], s = 0;
            #pragma unroll
            for (int i = 0; i < 8; i++) { c[i] = hist[lane * 8 + i]; s += c[i]; }
            unsigned int xs = s;
            #pragma unroll
            for (int o = 1; o < 32; o <<= 1) {
                unsigned int y = __shfl_up_sync(0xffffffffu, xs, o);
                if (lane >= o) xs += y;
            }
            unsigned int tt = __shfl_sync(0xffffffffu, xs, 31);
            unsigned int run = xs - s;
            #pragma unroll
            for (int i = 0; i < 8; i++) {
                unsigned int sfx = tt - run, after = sfx - c[i];
                if (sfx >= krem && after < krem) {
                    sh_sel = (unsigned int)(lane * 8 + i);
                    sh_krem = krem - after;
                    sh_done = (sfx == krem);
                }
                run += c[i];
            }
        }
        __syncthreads();
        pref |= (sh_sel << shift); maskH |= (0xFFu << shift);
        krem = sh_krem; done = sh_done;
        if (done) break;
    }
    const unsigned int T = pref;        // threshold in rebased (dk) domain
    const unsigned int R = done ? (unsigned int)K_ : krem;

    // contiguous-chunk ownership keeps array (= index) order for the rank scan
    const int ept = (cnt + THREADS - 1) / THREADS;   // usually 1
    const int beg = t * ept;
    int end = beg + ept; if (end > cnt) end = cnt;

    unsigned int gt = 0, eq = 0;
    for (int i = beg; i < end; i++) {
        unsigned int u = ckey[i];
        gt += (u > T);
        eq += (u == T);
    }
    unsigned int tot2;
    unsigned int pr = block_scan_excl(gt | (eq << 16), scanB, &tot2);
    unsigned int gtB = pr & 0xFFFFu;
    unsigned int eqB = pr >> 16;

    unsigned int j = gtB + ((eqB < R) ? eqB : R);
    unsigned int eqRank = eqB;
    const size_t idxBase = (size_t)blockIdx.x * K_;
    float* __restrict__ indRow = ind ? (ind + (size_t)b * K_ * D_) : nullptr;
    const float inv_n = 1.0f / (float)N_;

    for (int i = beg; i < end; i++) {
        unsigned int u = ckey[i];
        bool isEq = (u == T);
        bool sel  = (u > T) || (isEq && (eqRank < R));
        eqRank += isEq ? 1u : 0u;
        if (sel) {
            int e = (int)cidx[i];
            if (idxf) idxf[idxBase + j] = (float)e;
            if (indRow) atomicAdd(indRow + (size_t)j * D_ + e, inv_n);
            j++;
        }
    }
}

extern "C" void kernel_launch(void* const* d_in, const int* in_sizes, int n_in,
                              void* d_out, int out_size) {
    const float* x     = (const float*)d_in[0];
    const float* noise = (const float*)d_in[1];
    if (n_in >= 2 && in_sizes[0] != B_ * D_) {
        x     = (const float*)d_in[1];
        noise = (const float*)d_in[0];
    }

    const long long IND = (long long)B_ * K_ * D_;   // 8388608
    const long long IDX = (long long)B_ * N_ * K_;   // 2048000

    float* ind  = nullptr;
    float* idxf = nullptr;
    if ((long long)out_size >= IND + IDX) {
        ind  = (float*)d_out;
        idxf = (float*)d_out + IND;
    } else if ((long long)out_size == IND) {
        ind = (float*)d_out;
    } else if ((long long)out_size == IDX) {
        idxf = (float*)d_out;
    } else {
        ind = (float*)d_out;
    }

    prep_kernel<<<PREP_BLOCKS, THREADS>>>(x, (float4*)ind, (int)(IND / 4));
    perturbed_topk_kernel<<<B_ * N_, THREADS>>>(x, noise, ind, idxf);
}

// round 10
// speedup vs baseline: 1.6728x; 1.1063x over previous
#include <cuda_runtime.h>
#include <cstdint>

#define B_      32
#define N_      500
#define D_      2048
#define K_      128
#define SIGMA   0.05f
#define THREADS 256          // 8 contiguous elements per thread

__device__ float g_xk[B_];    // safe lower bound of K-th largest of x per row
__device__ float g_xmax[B_];  // max of x per row

// monotone float -> uint (bigger float -> bigger uint)
__device__ __forceinline__ unsigned int f2u(float f) {
    unsigned int u = __float_as_uint(f);
    return u ^ (((unsigned int)((int)u >> 31)) | 0x80000000u);
}
__device__ __forceinline__ float u2f(unsigned int u) {
    unsigned int v = (u & 0x80000000u) ? (u ^ 0x80000000u) : ~u;
    return __uint_as_float(v);
}

// exclusive block scan over 256 threads (8 warps); returns total.
// Dedicated warpSums buffer per call site; no trailing barrier.
__device__ __forceinline__ unsigned int block_scan_excl(unsigned int v,
                                                        unsigned int* warpSums,
                                                        unsigned int* total) {
    const int lane = threadIdx.x & 31;
    const int wid  = threadIdx.x >> 5;
    unsigned int x = v;
    #pragma unroll
    for (int o = 1; o < 32; o <<= 1) {
        unsigned int y = __shfl_up_sync(0xffffffffu, x, o);
        if (lane >= o) x += y;
    }
    if (lane == 31) warpSums[wid] = x;
    __syncthreads();
    if (wid == 0 && lane < 8) {
        unsigned int s = warpSums[lane];
        #pragma unroll
        for (int o = 1; o < 8; o <<= 1) {
            unsigned int y = __shfl_up_sync(0xffu, s, o);
            if (lane >= o) s += y;
        }
        warpSums[lane] = s;
    }
    __syncthreads();
    unsigned int base = (wid > 0) ? warpSums[wid - 1] : 0u;
    *total = warpSums[7];
    return base + x - v;
}

// ---- prep kernel: blocks 0..31 compute xK(row) + xmax(row); blocks 32.. zero `ind` ----
#define PREP_BLOCKS 2048
__global__ __launch_bounds__(THREADS)
void prep_kernel(const float* __restrict__ x, float4* __restrict__ ind4, int n4) {
    __shared__ unsigned int hist[256];
    __shared__ unsigned int warpMaxU[8];
    __shared__ unsigned int sh_sel, sh_krem, sh_done;

    const int t = threadIdx.x;

    if (blockIdx.x >= B_) {
        if (ind4) {
            float4 z = make_float4(0.f, 0.f, 0.f, 0.f);
            int stride = (PREP_BLOCKS - B_) * THREADS;
            for (int i = (blockIdx.x - B_) * THREADS + t; i < n4; i += stride)
                ind4[i] = z;
        }
        return;
    }

    const int lane = t & 31, wid = t >> 5;
    const int b = blockIdx.x;

    unsigned int k[8];
    unsigned int mu = 0u;
    {
        const float4* xv = (const float4*)(x + (size_t)b * D_);
        float4 a = xv[2 * t], c = xv[2 * t + 1];
        k[0] = f2u(a.x); k[1] = f2u(a.y); k[2] = f2u(a.z); k[3] = f2u(a.w);
        k[4] = f2u(c.x); k[5] = f2u(c.y); k[6] = f2u(c.z); k[7] = f2u(c.w);
        #pragma unroll
        for (int i = 0; i < 8; i++) mu = max(mu, k[i]);
    }
    #pragma unroll
    for (int o = 16; o > 0; o >>= 1)
        mu = max(mu, __shfl_xor_sync(0xffffffffu, mu, o));
    if (lane == 0) warpMaxU[wid] = mu;

    unsigned int pref = 0, maskH = 0, krem = K_, done = 0;
    for (int pass = 0; pass < 4; pass++) {
        const int shift = 24 - pass * 8;
        hist[t] = 0u;
        __syncthreads();
        #pragma unroll
        for (int i = 0; i < 8; i++) {
            unsigned int kk = k[i];
            if ((kk & maskH) == pref)
                atomicAdd(&hist[(kk >> shift) & 0xFFu], 1u);
        }
        __syncthreads();
        if (wid == 0) {
            unsigned int c[8], s = 0;
            #pragma unroll
            for (int i = 0; i < 8; i++) { c[i] = hist[lane * 8 + i]; s += c[i]; }
            unsigned int xs = s;
            #pragma unroll
            for (int o = 1; o < 32; o <<= 1) {
                unsigned int y = __shfl_up_sync(0xffffffffu, xs, o);
                if (lane >= o) xs += y;
            }
            unsigned int tot = __shfl_sync(0xffffffffu, xs, 31);
            unsigned int run = xs - s;
            #pragma unroll
            for (int i = 0; i < 8; i++) {
                unsigned int sfx = tot - run, after = sfx - c[i];
                if (sfx >= krem && after < krem) {
                    sh_sel = (unsigned int)(lane * 8 + i);
                    sh_krem = krem - after;
                    sh_done = (sfx == krem);
                }
                run += c[i];
            }
        }
        __syncthreads();
        pref |= (sh_sel << shift); maskH |= (0xFFu << shift);
        krem = sh_krem; done = sh_done;
        if (done) break;
    }
    if (t == 0) {
        g_xk[b] = u2f(pref);
        unsigned int M = warpMaxU[0];
        #pragma unroll
        for (int w = 1; w < 8; w++) M = max(M, warpMaxU[w]);
        g_xmax[b] = u2f(M);
    }
}

// ---- main kernel: one CTA per (b, n) sample ----
__global__ __launch_bounds__(THREADS, 8)
void perturbed_topk_kernel(const float* __restrict__ x,
                           const float* __restrict__ noise,
                           float* __restrict__ ind,    // (B,K,D) or null
                           float* __restrict__ idxf)   // (B,N,K) or null
{
    __shared__ unsigned int   ckey[D_];
    __shared__ unsigned short cidx[D_];
    __shared__ unsigned int   hist[256];
    __shared__ unsigned int   scanA[8], scanB[8];
    __shared__ float          warpMaxN[8];
    __shared__ float          sh_L;
    __shared__ unsigned int   sh_Lu;
    __shared__ int            sh_p0;
    __shared__ unsigned int   sh_sel, sh_krem, sh_done;

    const int t = threadIdx.x, lane = t & 31, wid = t >> 5;
    const int b = blockIdx.x / N_;

    // load + perturb (thread t owns elems 8t..8t+7); track max|noise|
    float kf[8];
    float am = 0.f;
    {
        const float4* xv = (const float4*)(x + (size_t)b * D_);
        const float4* nv = (const float4*)(noise + (size_t)blockIdx.x * D_);
        float4 X0 = xv[2 * t], X1 = xv[2 * t + 1];
        float4 N0 = nv[2 * t], N1 = nv[2 * t + 1];
        kf[0] = fmaf(SIGMA, N0.x, X0.x); am = fmaxf(am, fabsf(N0.x));
        kf[1] = fmaf(SIGMA, N0.y, X0.y); am = fmaxf(am, fabsf(N0.y));
        kf[2] = fmaf(SIGMA, N0.z, X0.z); am = fmaxf(am, fabsf(N0.z));
        kf[3] = fmaf(SIGMA, N0.w, X0.w); am = fmaxf(am, fabsf(N0.w));
        kf[4] = fmaf(SIGMA, N1.x, X1.x); am = fmaxf(am, fabsf(N1.x));
        kf[5] = fmaf(SIGMA, N1.y, X1.y); am = fmaxf(am, fabsf(N1.y));
        kf[6] = fmaf(SIGMA, N1.z, X1.z); am = fmaxf(am, fabsf(N1.z));
        kf[7] = fmaf(SIGMA, N1.w, X1.w); am = fmaxf(am, fabsf(N1.w));
    }
    #pragma unroll
    for (int o = 16; o > 0; o >>= 1)
        am = fmaxf(am, __shfl_xor_sync(0xffffffffu, am, o));
    if (lane == 0) warpMaxN[wid] = am;
    __syncthreads();
    if (t == 0) {
        float m = warpMaxN[0];
        #pragma unroll
        for (int w = 1; w < 8; w++) m = fmaxf(m, warpMaxN[w]);
        float L = g_xk[b] - SIGMA * m - 1e-4f;       // lower bound on K-th key
        float Mup = g_xmax[b] + SIGMA * m + 1e-4f;   // upper bound on max key
        unsigned int Lu = f2u(L);
        unsigned int spread = f2u(Mup) - Lu;         // candidate dk in [0, spread]
        sh_L  = L;
        sh_Lu = Lu;
        sh_p0 = (spread >> 24) ? 0 : ((spread >> 16) ? 1 : ((spread >> 8) ? 2 : 3));
    }
    __syncthreads();
    const float L = sh_L;
    const unsigned int Lu = sh_Lu;

    // candidate mask in float domain (f2u deferred to compaction)
    unsigned int m8 = 0;
    #pragma unroll
    for (int i = 0; i < 8; i++)
        m8 |= (kf[i] >= L) ? (1u << i) : 0u;

    unsigned int tot;
    unsigned int pos = block_scan_excl(__popc(m8), scanA, &tot);
    const int cnt = (int)tot;          // >= K guaranteed, <= 2048

    unsigned int mm = m8;
    while (mm) {
        int i = __ffs(mm) - 1;
        mm &= mm - 1;
        ckey[pos] = f2u(kf[i]) - Lu;   // rebased keys: order preserved, high bytes 0
        cidx[pos] = (unsigned short)(8 * t + i);
        pos++;
    }
    __syncthreads();

    // radix select over cnt rebased candidates, starting at first possibly-nonzero byte
    const int p0 = sh_p0;
    unsigned int pref = 0;
    unsigned int maskH = (p0 > 0) ? (0xFFFFFFFFu << (32 - 8 * p0)) : 0u;
    unsigned int krem = K_, done = 0;

    for (int pass = p0; pass < 4; pass++) {
        const int shift = 24 - pass * 8;
        hist[t] = 0u;
        __syncthreads();
        for (int i = t; i < cnt; i += THREADS) {
            unsigned int u = ckey[i];
            if ((u & maskH) == pref)
                atomicAdd(&hist[(u >> shift) & 0xFFu], 1u);
        }
        __syncthreads();
        if (wid == 0) {
            unsigned int c[8], s = 0;
            #pragma unroll
            for (int i = 0; i < 8; i++) { c[i] = hist[lane * 8 + i]; s += c[i]; }
            unsigned int xs = s;
            #pragma unroll
            for (int o = 1; o < 32; o <<= 1) {
                unsigned int y = __shfl_up_sync(0xffffffffu, xs, o);
                if (lane >= o) xs += y;
            }
            unsigned int tt = __shfl_sync(0xffffffffu, xs, 31);
            unsigned int run = xs - s;
            #pragma unroll
            for (int i = 0; i < 8; i++) {
                unsigned int sfx = tt - run, after = sfx - c[i];
                if (sfx >= krem && after < krem) {
                    sh_sel = (unsigned int)(lane * 8 + i);
                    sh_krem = krem - after;
                    sh_done = (sfx == krem);
                }
                run += c[i];
            }
        }
        __syncthreads();
        pref |= (sh_sel << shift); maskH |= (0xFFu << shift);
        krem = sh_krem; done = sh_done;
        if (done) break;
    }
    const unsigned int T = pref;        // threshold in rebased (dk) domain
    const unsigned int R = done ? (unsigned int)K_ : krem;

    // contiguous-chunk ownership keeps array (= index) order for the rank scan
    const int ept = (cnt + THREADS - 1) / THREADS;   // usually 1
    const int beg = t * ept;
    int end = beg + ept; if (end > cnt) end = cnt;

    unsigned int gt = 0, eq = 0;
    for (int i = beg; i < end; i++) {
        unsigned int u = ckey[i];
        gt += (u > T);
        eq += (u == T);
    }
    unsigned int tot2;
    unsigned int pr = block_scan_excl(gt | (eq << 16), scanB, &tot2);
    unsigned int gtB = pr & 0xFFFFu;
    unsigned int eqB = pr >> 16;

    unsigned int j = gtB + ((eqB < R) ? eqB : R);
    unsigned int eqRank = eqB;
    const size_t idxBase = (size_t)blockIdx.x * K_;
    float* __restrict__ indRow = ind ? (ind + (size_t)b * K_ * D_) : nullptr;
    const float inv_n = 1.0f / (float)N_;

    for (int i = beg; i < end; i++) {
        unsigned int u = ckey[i];
        bool isEq = (u == T);
        bool sel  = (u > T) || (isEq && (eqRank < R));
        eqRank += isEq ? 1u : 0u;
        if (sel) {
            int e = (int)cidx[i];
            if (idxf) idxf[idxBase + j] = (float)e;
            if (indRow) atomicAdd(indRow + (size_t)j * D_ + e, inv_n);
            j++;
        }
    }
}

extern "C" void kernel_launch(void* const* d_in, const int* in_sizes, int n_in,
                              void* d_out, int out_size) {
    const float* x     = (const float*)d_in[0];
    const float* noise = (const float*)d_in[1];
    if (n_in >= 2 && in_sizes[0] != B_ * D_) {
        x     = (const float*)d_in[1];
        noise = (const float*)d_in[0];
    }

    const long long IND = (long long)B_ * K_ * D_;   // 8388608
    const long long IDX = (long long)B_ * N_ * K_;   // 2048000

    float* ind  = nullptr;
    float* idxf = nullptr;
    if ((long long)out_size >= IND + IDX) {
        ind  = (float*)d_out;
        idxf = (float*)d_out + IND;
    } else if ((long long)out_size == IND) {
        ind = (float*)d_out;
    } else if ((long long)out_size == IDX) {
        idxf = (float*)d_out;
    } else {
        ind = (float*)d_out;
    }

    prep_kernel<<<PREP_BLOCKS, THREADS>>>(x, (float4*)ind, (int)(IND / 4));
    perturbed_topk_kernel<<<B_ * N_, THREADS>>>(x, noise, ind, idxf);
}